// round 15
// baseline (speedup 1.0000x reference)
#include <cuda_runtime.h>
#include <math.h>

// NTM memory addressing + read/write.  (FINAL converged design — best measured)
// grid=8192, chunked cp.async.bulk tile load (8 x 4KB, parallel issue, interleaved
// waits), in-place erase/add in smem + single 32KB cp.async.bulk store-out,
// MUFU fast-math single-warp mid-phase, 6 CTAs/SM.
// Inputs: memory(B,N,M) prev_w(B,N) k(B,M) beta(B,1) g(B,1) s(3) y(B,1) e(B,M) a(B,M)
// Output layout: read(B,M) | mem_new(B,N,M) | w(B,N);  B=8192, N=128, M=64

#define BB 8192
#define NN 128
#define MM 64
#define CHUNK_BYTES 4096      // 256 float4
#define NCHUNK 8
#define TILE_BYTES 32768

__device__ __forceinline__ unsigned su32(const void* p) {
    return (unsigned)__cvta_generic_to_shared(p);
}
__device__ __forceinline__ void mbar_init(unsigned m, unsigned c) {
    asm volatile("mbarrier.init.shared.b64 [%0], %1;" :: "r"(m), "r"(c) : "memory");
}
__device__ __forceinline__ void mbar_expect_tx(unsigned m, unsigned bytes) {
    asm volatile("mbarrier.arrive.expect_tx.shared.b64 _, [%0], %1;"
                 :: "r"(m), "r"(bytes) : "memory");
}
__device__ __forceinline__ void bulk_ld(unsigned dst, const void* src, unsigned bytes, unsigned m) {
    asm volatile("cp.async.bulk.shared::cta.global.mbarrier::complete_tx::bytes [%0], [%1], %2, [%3];"
                 :: "r"(dst), "l"(src), "r"(bytes), "r"(m) : "memory");
}
__device__ __forceinline__ void bulk_st(void* gdst, unsigned ssrc, unsigned bytes) {
    asm volatile("cp.async.bulk.global.shared::cta.bulk_group [%0], [%1], %2;"
                 :: "l"(gdst), "r"(ssrc), "r"(bytes) : "memory");
}
__device__ __forceinline__ void bulk_st_commit() {
    asm volatile("cp.async.bulk.commit_group;" ::: "memory");
}
__device__ __forceinline__ void bulk_st_wait_read() {
    asm volatile("cp.async.bulk.wait_group.read 0;" ::: "memory");
}
__device__ __forceinline__ void mbar_wait0(unsigned m) {
    asm volatile("{\n\t"
                 ".reg .pred P;\n\t"
                 "W:\n\t"
                 "mbarrier.try_wait.parity.acquire.cta.shared::cta.b64 P, [%0], 0;\n\t"
                 "@!P bra W;\n\t"
                 "}" :: "r"(m) : "memory");
}
__device__ __forceinline__ void pref_l2(const void* p) {
    asm volatile("prefetch.global.L2 [%0];" :: "l"(p));
}
__device__ __forceinline__ void st_cs_f(float* p, float v) {
    asm volatile("st.global.cs.f32 [%0], %1;" :: "l"(p), "f"(v) : "memory");
}
__device__ __forceinline__ void st_cs_f4(float4* p, float4 v) {
    asm volatile("st.global.cs.v4.f32 [%0], {%1,%2,%3,%4};"
                 :: "l"(p), "f"(v.x), "f"(v.y), "f"(v.z), "f"(v.w) : "memory");
}

__device__ __forceinline__ float red16(float v) {
    v += __shfl_xor_sync(0xffffffffu, v, 8);
    v += __shfl_xor_sync(0xffffffffu, v, 4);
    v += __shfl_xor_sync(0xffffffffu, v, 2);
    v += __shfl_xor_sync(0xffffffffu, v, 1);
    return v;
}

__global__ __launch_bounds__(256, 6) void ntm_kernel(
    const float4* __restrict__ memory,
    const float4* __restrict__ prev_w4,
    const float4* __restrict__ k,
    const float*  __restrict__ beta,
    const float*  __restrict__ g,
    const float*  __restrict__ s,
    const float*  __restrict__ y,
    const float4* __restrict__ e4,
    const float4* __restrict__ a4,
    float*  __restrict__ out_read,
    float4* __restrict__ out_mem,
    float4* __restrict__ out_w4)
{
    __shared__ float4 tile[2048];          // 32 KB (updated in place, bulk-stored)
    __shared__ float4 rbuf4[128];          // 2 KB (warp-half-reduced partials)
    __shared__ float  logit[NN];
    __shared__ float  swf[NN];
    __shared__ unsigned long long mbar[NCHUNK];

    const int b  = blockIdx.x;
    const int t  = threadIdx.x;
    const int gg = t & 15;                 // quad-column owned
    const int j  = t >> 4;                 // rows n = 16*i + j
    const int lane = t & 31;
    const int wrp  = t >> 5;

    if (t < NCHUNK) mbar_init(su32(&mbar[t]), 1);
    __syncthreads();
    if (t < NCHUNK) {
        // each of 8 threads issues its own chunk: parallel DMA issuance
        const float4* src = memory + (size_t)b * 2048 + t * 256;
        unsigned m = su32(&mbar[t]);
        mbar_expect_tx(m, CHUNK_BYTES);
        bulk_ld(su32(&tile[t * 256]), src, CHUNK_BYTES, m);
    }

    // prefetch small operands while the bulk copies are in flight
    pref_l2(&e4[b * 16 + gg]);
    pref_l2(&a4[b * 16 + gg]);
    const float4 kq = __ldg(&k[b * 16 + gg]);
    float betab = 0.f, gb = 0.f, yb = 0.f, s0 = 0.f, s1 = 0.f, s2 = 0.f;
    float4 pw = make_float4(0.f, 0.f, 0.f, 0.f);
    if (t < 32) {
        betab = __ldg(&beta[b]); gb = __ldg(&g[b]); yb = __ldg(&y[b]);
        s0 = __ldg(&s[0]); s1 = __ldg(&s[1]); s2 = __ldg(&s[2]);
        pw = __ldg(&prev_w4[b * 32 + t]);
    }

    // --- pass 1: per-row dot & |m|^2, chunk-interleaved waits (1 iter/chunk) ---
    {
        float ksq   = red16(kq.x*kq.x + kq.y*kq.y + kq.z*kq.z + kq.w*kq.w);
        float knorm = fmaxf(sqrtf(ksq), 1e-8f);
        #pragma unroll
        for (int i = 0; i < NCHUNK; i++) {
            mbar_wait0(su32(&mbar[i]));
            float4 vv = tile[i * 256 + t];
            float d  = vv.x*kq.x + vv.y*kq.y + vv.z*kq.z + vv.w*kq.w;
            float ms = vv.x*vv.x + vv.y*vv.y + vv.z*vv.z + vv.w*vv.w;
            d  = red16(d);
            ms = red16(ms);
            if (gg == 2 * i)
                logit[16 * i + j] = d / (knorm * fmaxf(sqrtf(ms), 1e-8f));
        }
    }
    __syncthreads();

    // --- mid-phase: warp 0 only, lane l owns rows 4l..4l+3 (MUFU fast-math) ---
    if (t < 32) {
        const float4 lg = ((const float4*)logit)[t];
        float l0 = betab * lg.x, l1 = betab * lg.y,
              l2 = betab * lg.z, l3 = betab * lg.w;

        float mx = fmaxf(fmaxf(l0, l1), fmaxf(l2, l3));
        #pragma unroll
        for (int o = 16; o; o >>= 1) mx = fmaxf(mx, __shfl_xor_sync(0xffffffffu, mx, o));

        float e0 = __expf(l0 - mx), e1 = __expf(l1 - mx),
              e2 = __expf(l2 - mx), e3 = __expf(l3 - mx);
        float sden = (e0 + e1) + (e2 + e3);
        #pragma unroll
        for (int o = 16; o; o >>= 1) sden += __shfl_xor_sync(0xffffffffu, sden, o);
        float inv = 1.f / sden;
        float og = 1.f - gb;

        float w0 = gb * e0 * inv + og * pw.x;
        float w1 = gb * e1 * inv + og * pw.y;
        float w2 = gb * e2 * inv + og * pw.z;
        float w3 = gb * e3 * inv + og * pw.w;

        float left  = __shfl_sync(0xffffffffu, w3, (t + 31) & 31);
        float right = __shfl_sync(0xffffffffu, w0, (t + 1) & 31);

        float wt0 = s0 * left + s1 * w0 + s2 * w1;
        float wt1 = s0 * w0   + s1 * w1 + s2 * w2;
        float wt2 = s0 * w1   + s1 * w2 + s2 * w3;
        float wt3 = s0 * w2   + s1 * w3 + s2 * right;

        float p0 = __powf(wt0, yb), p1 = __powf(wt1, yb),
              p2 = __powf(wt2, yb), p3 = __powf(wt3, yb);
        float psum = (p0 + p1) + (p2 + p3);
        #pragma unroll
        for (int o = 16; o; o >>= 1) psum += __shfl_xor_sync(0xffffffffu, psum, o);
        float ip = 1.f / psum;

        float4 wf = make_float4(p0 * ip, p1 * ip, p2 * ip, p3 * ip);
        ((float4*)swf)[t] = wf;
        st_cs_f4(&out_w4[b * 32 + t], wf);
    }
    __syncthreads();

    // --- erase/add in place (LDS.128 + STS.128) + read accumulation ---
    {
        const float4 eq = __ldg(&e4[b * 16 + gg]);
        const float4 aq = __ldg(&a4[b * 16 + gg]);
        float4 racc = make_float4(0.f, 0.f, 0.f, 0.f);
        #pragma unroll
        for (int i = 0; i < 8; i++) {
            float wn = swf[16 * i + j];
            float4 vv = tile[i * 256 + t], o;
            o.x = vv.x * (1.f - wn * eq.x) + wn * aq.x;
            o.y = vv.y * (1.f - wn * eq.y) + wn * aq.y;
            o.z = vv.z * (1.f - wn * eq.z) + wn * aq.z;
            o.w = vv.w * (1.f - wn * eq.w) + wn * aq.w;
            tile[i * 256 + t] = o;         // in-place: same word, no hazard
            racc.x += wn * vv.x; racc.y += wn * vv.y;
            racc.z += wn * vv.z; racc.w += wn * vv.w;
        }
        // merge the two j-phases within each warp (lanes l and l+16 share gg)
        racc.x += __shfl_xor_sync(0xffffffffu, racc.x, 16);
        racc.y += __shfl_xor_sync(0xffffffffu, racc.y, 16);
        racc.z += __shfl_xor_sync(0xffffffffu, racc.z, 16);
        racc.w += __shfl_xor_sync(0xffffffffu, racc.w, 16);
        if (lane < 16) rbuf4[wrp * 16 + lane] = racc;
    }
    __syncthreads();

    // final read reduction first (overlaps with TMA store issue below)
    float rfin = 0.f;
    if (t < MM) {
        const float* rb = (const float*)rbuf4;
        #pragma unroll
        for (int w = 0; w < 8; w++) rfin += rb[w * 64 + t];
    }

    // one bulk store drains the whole updated tile via the TMA engine
    if (t == 0) {
        bulk_st(out_mem + (size_t)b * 2048, su32(tile), TILE_BYTES);
        bulk_st_commit();
    }

    if (t < MM) st_cs_f(&out_read[b * MM + t], rfin);

    // smem must stay live until TMA has read it
    if (t == 0) bulk_st_wait_read();
}

extern "C" void kernel_launch(void* const* d_in, const int* in_sizes, int n_in,
                              void* d_out, int out_size)
{
    const float4* memory = (const float4*)d_in[0];
    const float4* prev_w = (const float4*)d_in[1];
    const float4* k      = (const float4*)d_in[2];
    const float*  beta   = (const float*)d_in[3];
    const float*  g      = (const float*)d_in[4];
    const float*  s      = (const float*)d_in[5];
    const float*  y      = (const float*)d_in[6];
    const float4* e      = (const float4*)d_in[7];
    const float4* a      = (const float4*)d_in[8];

    float* out = (float*)d_out;
    float*  out_read = out;
    float4* out_mem  = (float4*)(out + (size_t)BB * MM);
    float4* out_w    = (float4*)(out + (size_t)BB * MM + (size_t)BB * NN * MM);

    ntm_kernel<<<BB, 256>>>(memory, prev_w, k, beta, g, s, y, e, a,
                            out_read, out_mem, out_w);
}

// round 16
// speedup vs baseline: 1.0022x; 1.0022x over previous
#include <cuda_runtime.h>
#include <math.h>

// NTM memory addressing + read/write.  (FINAL converged design — best measured)
// grid=8192, chunked cp.async.bulk tile load (8 x 4KB, parallel issue, interleaved
// waits), in-place erase/add in smem + single 32KB cp.async.bulk store-out,
// MUFU fast-math single-warp mid-phase, 6 CTAs/SM.
// Inputs: memory(B,N,M) prev_w(B,N) k(B,M) beta(B,1) g(B,1) s(3) y(B,1) e(B,M) a(B,M)
// Output layout: read(B,M) | mem_new(B,N,M) | w(B,N);  B=8192, N=128, M=64

#define BB 8192
#define NN 128
#define MM 64
#define CHUNK_BYTES 4096      // 256 float4
#define NCHUNK 8
#define TILE_BYTES 32768

__device__ __forceinline__ unsigned su32(const void* p) {
    return (unsigned)__cvta_generic_to_shared(p);
}
__device__ __forceinline__ void mbar_init(unsigned m, unsigned c) {
    asm volatile("mbarrier.init.shared.b64 [%0], %1;" :: "r"(m), "r"(c) : "memory");
}
__device__ __forceinline__ void mbar_expect_tx(unsigned m, unsigned bytes) {
    asm volatile("mbarrier.arrive.expect_tx.shared.b64 _, [%0], %1;"
                 :: "r"(m), "r"(bytes) : "memory");
}
__device__ __forceinline__ void bulk_ld(unsigned dst, const void* src, unsigned bytes, unsigned m) {
    asm volatile("cp.async.bulk.shared::cta.global.mbarrier::complete_tx::bytes [%0], [%1], %2, [%3];"
                 :: "r"(dst), "l"(src), "r"(bytes), "r"(m) : "memory");
}
__device__ __forceinline__ void bulk_st(void* gdst, unsigned ssrc, unsigned bytes) {
    asm volatile("cp.async.bulk.global.shared::cta.bulk_group [%0], [%1], %2;"
                 :: "l"(gdst), "r"(ssrc), "r"(bytes) : "memory");
}
__device__ __forceinline__ void bulk_st_commit() {
    asm volatile("cp.async.bulk.commit_group;" ::: "memory");
}
__device__ __forceinline__ void bulk_st_wait_read() {
    asm volatile("cp.async.bulk.wait_group.read 0;" ::: "memory");
}
__device__ __forceinline__ void mbar_wait0(unsigned m) {
    asm volatile("{\n\t"
                 ".reg .pred P;\n\t"
                 "W:\n\t"
                 "mbarrier.try_wait.parity.acquire.cta.shared::cta.b64 P, [%0], 0;\n\t"
                 "@!P bra W;\n\t"
                 "}" :: "r"(m) : "memory");
}
__device__ __forceinline__ void pref_l2(const void* p) {
    asm volatile("prefetch.global.L2 [%0];" :: "l"(p));
}
__device__ __forceinline__ void st_cs_f(float* p, float v) {
    asm volatile("st.global.cs.f32 [%0], %1;" :: "l"(p), "f"(v) : "memory");
}
__device__ __forceinline__ void st_cs_f4(float4* p, float4 v) {
    asm volatile("st.global.cs.v4.f32 [%0], {%1,%2,%3,%4};"
                 :: "l"(p), "f"(v.x), "f"(v.y), "f"(v.z), "f"(v.w) : "memory");
}

__device__ __forceinline__ float red16(float v) {
    v += __shfl_xor_sync(0xffffffffu, v, 8);
    v += __shfl_xor_sync(0xffffffffu, v, 4);
    v += __shfl_xor_sync(0xffffffffu, v, 2);
    v += __shfl_xor_sync(0xffffffffu, v, 1);
    return v;
}

__global__ __launch_bounds__(256, 6) void ntm_kernel(
    const float4* __restrict__ memory,
    const float4* __restrict__ prev_w4,
    const float4* __restrict__ k,
    const float*  __restrict__ beta,
    const float*  __restrict__ g,
    const float*  __restrict__ s,
    const float*  __restrict__ y,
    const float4* __restrict__ e4,
    const float4* __restrict__ a4,
    float*  __restrict__ out_read,
    float4* __restrict__ out_mem,
    float4* __restrict__ out_w4)
{
    __shared__ float4 tile[2048];          // 32 KB (updated in place, bulk-stored)
    __shared__ float4 rbuf4[128];          // 2 KB (warp-half-reduced partials)
    __shared__ float  logit[NN];
    __shared__ float  swf[NN];
    __shared__ unsigned long long mbar[NCHUNK];

    const int b  = blockIdx.x;
    const int t  = threadIdx.x;
    const int gg = t & 15;                 // quad-column owned
    const int j  = t >> 4;                 // rows n = 16*i + j
    const int lane = t & 31;
    const int wrp  = t >> 5;

    if (t < NCHUNK) mbar_init(su32(&mbar[t]), 1);
    __syncthreads();
    if (t < NCHUNK) {
        // each of 8 threads issues its own chunk: parallel DMA issuance
        const float4* src = memory + (size_t)b * 2048 + t * 256;
        unsigned m = su32(&mbar[t]);
        mbar_expect_tx(m, CHUNK_BYTES);
        bulk_ld(su32(&tile[t * 256]), src, CHUNK_BYTES, m);
    }

    // prefetch small operands while the bulk copies are in flight
    pref_l2(&e4[b * 16 + gg]);
    pref_l2(&a4[b * 16 + gg]);
    const float4 kq = __ldg(&k[b * 16 + gg]);
    float betab = 0.f, gb = 0.f, yb = 0.f, s0 = 0.f, s1 = 0.f, s2 = 0.f;
    float4 pw = make_float4(0.f, 0.f, 0.f, 0.f);
    if (t < 32) {
        betab = __ldg(&beta[b]); gb = __ldg(&g[b]); yb = __ldg(&y[b]);
        s0 = __ldg(&s[0]); s1 = __ldg(&s[1]); s2 = __ldg(&s[2]);
        pw = __ldg(&prev_w4[b * 32 + t]);
    }

    // --- pass 1: per-row dot & |m|^2, chunk-interleaved waits (1 iter/chunk) ---
    {
        float ksq   = red16(kq.x*kq.x + kq.y*kq.y + kq.z*kq.z + kq.w*kq.w);
        float knorm = fmaxf(sqrtf(ksq), 1e-8f);
        #pragma unroll
        for (int i = 0; i < NCHUNK; i++) {
            mbar_wait0(su32(&mbar[i]));
            float4 vv = tile[i * 256 + t];
            float d  = vv.x*kq.x + vv.y*kq.y + vv.z*kq.z + vv.w*kq.w;
            float ms = vv.x*vv.x + vv.y*vv.y + vv.z*vv.z + vv.w*vv.w;
            d  = red16(d);
            ms = red16(ms);
            if (gg == 2 * i)
                logit[16 * i + j] = d / (knorm * fmaxf(sqrtf(ms), 1e-8f));
        }
    }
    __syncthreads();

    // --- mid-phase: warp 0 only, lane l owns rows 4l..4l+3 (MUFU fast-math) ---
    if (t < 32) {
        const float4 lg = ((const float4*)logit)[t];
        float l0 = betab * lg.x, l1 = betab * lg.y,
              l2 = betab * lg.z, l3 = betab * lg.w;

        float mx = fmaxf(fmaxf(l0, l1), fmaxf(l2, l3));
        #pragma unroll
        for (int o = 16; o; o >>= 1) mx = fmaxf(mx, __shfl_xor_sync(0xffffffffu, mx, o));

        float e0 = __expf(l0 - mx), e1 = __expf(l1 - mx),
              e2 = __expf(l2 - mx), e3 = __expf(l3 - mx);
        float sden = (e0 + e1) + (e2 + e3);
        #pragma unroll
        for (int o = 16; o; o >>= 1) sden += __shfl_xor_sync(0xffffffffu, sden, o);
        float inv = 1.f / sden;
        float og = 1.f - gb;

        float w0 = gb * e0 * inv + og * pw.x;
        float w1 = gb * e1 * inv + og * pw.y;
        float w2 = gb * e2 * inv + og * pw.z;
        float w3 = gb * e3 * inv + og * pw.w;

        float left  = __shfl_sync(0xffffffffu, w3, (t + 31) & 31);
        float right = __shfl_sync(0xffffffffu, w0, (t + 1) & 31);

        float wt0 = s0 * left + s1 * w0 + s2 * w1;
        float wt1 = s0 * w0   + s1 * w1 + s2 * w2;
        float wt2 = s0 * w1   + s1 * w2 + s2 * w3;
        float wt3 = s0 * w2   + s1 * w3 + s2 * right;

        float p0 = __powf(wt0, yb), p1 = __powf(wt1, yb),
              p2 = __powf(wt2, yb), p3 = __powf(wt3, yb);
        float psum = (p0 + p1) + (p2 + p3);
        #pragma unroll
        for (int o = 16; o; o >>= 1) psum += __shfl_xor_sync(0xffffffffu, psum, o);
        float ip = 1.f / psum;

        float4 wf = make_float4(p0 * ip, p1 * ip, p2 * ip, p3 * ip);
        ((float4*)swf)[t] = wf;
        st_cs_f4(&out_w4[b * 32 + t], wf);
    }
    __syncthreads();

    // --- erase/add in place (LDS.128 + STS.128) + read accumulation ---
    {
        const float4 eq = __ldg(&e4[b * 16 + gg]);
        const float4 aq = __ldg(&a4[b * 16 + gg]);
        float4 racc = make_float4(0.f, 0.f, 0.f, 0.f);
        #pragma unroll
        for (int i = 0; i < 8; i++) {
            float wn = swf[16 * i + j];
            float4 vv = tile[i * 256 + t], o;
            o.x = vv.x * (1.f - wn * eq.x) + wn * aq.x;
            o.y = vv.y * (1.f - wn * eq.y) + wn * aq.y;
            o.z = vv.z * (1.f - wn * eq.z) + wn * aq.z;
            o.w = vv.w * (1.f - wn * eq.w) + wn * aq.w;
            tile[i * 256 + t] = o;         // in-place: same word, no hazard
            racc.x += wn * vv.x; racc.y += wn * vv.y;
            racc.z += wn * vv.z; racc.w += wn * vv.w;
        }
        // merge the two j-phases within each warp (lanes l and l+16 share gg)
        racc.x += __shfl_xor_sync(0xffffffffu, racc.x, 16);
        racc.y += __shfl_xor_sync(0xffffffffu, racc.y, 16);
        racc.z += __shfl_xor_sync(0xffffffffu, racc.z, 16);
        racc.w += __shfl_xor_sync(0xffffffffu, racc.w, 16);
        if (lane < 16) rbuf4[wrp * 16 + lane] = racc;
    }
    __syncthreads();

    // final read reduction first (overlaps with TMA store issue below)
    float rfin = 0.f;
    if (t < MM) {
        const float* rb = (const float*)rbuf4;
        #pragma unroll
        for (int w = 0; w < 8; w++) rfin += rb[w * 64 + t];
    }

    // one bulk store drains the whole updated tile via the TMA engine
    if (t == 0) {
        bulk_st(out_mem + (size_t)b * 2048, su32(tile), TILE_BYTES);
        bulk_st_commit();
    }

    if (t < MM) st_cs_f(&out_read[b * MM + t], rfin);

    // smem must stay live until TMA has read it
    if (t == 0) bulk_st_wait_read();
}

extern "C" void kernel_launch(void* const* d_in, const int* in_sizes, int n_in,
                              void* d_out, int out_size)
{
    const float4* memory = (const float4*)d_in[0];
    const float4* prev_w = (const float4*)d_in[1];
    const float4* k      = (const float4*)d_in[2];
    const float*  beta   = (const float*)d_in[3];
    const float*  g      = (const float*)d_in[4];
    const float*  s      = (const float*)d_in[5];
    const float*  y      = (const float*)d_in[6];
    const float4* e      = (const float4*)d_in[7];
    const float4* a      = (const float4*)d_in[8];

    float* out = (float*)d_out;
    float*  out_read = out;
    float4* out_mem  = (float4*)(out + (size_t)BB * MM);
    float4* out_w    = (float4*)(out + (size_t)BB * MM + (size_t)BB * NN * MM);

    ntm_kernel<<<BB, 256>>>(memory, prev_w, k, beta, g, s, y, e, a,
                            out_read, out_mem, out_w);
}

// round 17
// speedup vs baseline: 1.0112x; 1.0089x over previous
#include <cuda_runtime.h>
#include <math.h>

// NTM memory addressing + read/write.  (converged design + L2 evict_first hints)
// grid=8192, chunked cp.async.bulk tile load (8 x 4KB, parallel issue, interleaved
// waits, L2::evict_first), in-place erase/add in smem + single 32KB cp.async.bulk
// store-out (L2::evict_first), MUFU fast-math single-warp mid-phase, 6 CTAs/SM.
// Inputs: memory(B,N,M) prev_w(B,N) k(B,M) beta(B,1) g(B,1) s(3) y(B,1) e(B,M) a(B,M)
// Output layout: read(B,M) | mem_new(B,N,M) | w(B,N);  B=8192, N=128, M=64

#define BB 8192
#define NN 128
#define MM 64
#define CHUNK_BYTES 4096      // 256 float4
#define NCHUNK 8
#define TILE_BYTES 32768

__device__ __forceinline__ unsigned su32(const void* p) {
    return (unsigned)__cvta_generic_to_shared(p);
}
__device__ __forceinline__ unsigned long long mk_evict_first() {
    unsigned long long pol;
    asm("createpolicy.fractional.L2::evict_first.b64 %0, 1.0;" : "=l"(pol));
    return pol;
}
__device__ __forceinline__ void mbar_init(unsigned m, unsigned c) {
    asm volatile("mbarrier.init.shared.b64 [%0], %1;" :: "r"(m), "r"(c) : "memory");
}
__device__ __forceinline__ void mbar_expect_tx(unsigned m, unsigned bytes) {
    asm volatile("mbarrier.arrive.expect_tx.shared.b64 _, [%0], %1;"
                 :: "r"(m), "r"(bytes) : "memory");
}
__device__ __forceinline__ void bulk_ld_pol(unsigned dst, const void* src, unsigned bytes,
                                            unsigned m, unsigned long long pol) {
    asm volatile("cp.async.bulk.shared::cta.global.mbarrier::complete_tx::bytes.L2::cache_hint"
                 " [%0], [%1], %2, [%3], %4;"
                 :: "r"(dst), "l"(src), "r"(bytes), "r"(m), "l"(pol) : "memory");
}
__device__ __forceinline__ void bulk_st_pol(void* gdst, unsigned ssrc, unsigned bytes,
                                            unsigned long long pol) {
    asm volatile("cp.async.bulk.global.shared::cta.bulk_group.L2::cache_hint [%0], [%1], %2, %3;"
                 :: "l"(gdst), "r"(ssrc), "r"(bytes), "l"(pol) : "memory");
}
__device__ __forceinline__ void bulk_st_commit() {
    asm volatile("cp.async.bulk.commit_group;" ::: "memory");
}
__device__ __forceinline__ void bulk_st_wait_read() {
    asm volatile("cp.async.bulk.wait_group.read 0;" ::: "memory");
}
__device__ __forceinline__ void mbar_wait0(unsigned m) {
    asm volatile("{\n\t"
                 ".reg .pred P;\n\t"
                 "W:\n\t"
                 "mbarrier.try_wait.parity.acquire.cta.shared::cta.b64 P, [%0], 0;\n\t"
                 "@!P bra W;\n\t"
                 "}" :: "r"(m) : "memory");
}
__device__ __forceinline__ void pref_l2(const void* p) {
    asm volatile("prefetch.global.L2 [%0];" :: "l"(p));
}
__device__ __forceinline__ void st_cs_f(float* p, float v) {
    asm volatile("st.global.cs.f32 [%0], %1;" :: "l"(p), "f"(v) : "memory");
}
__device__ __forceinline__ void st_cs_f4(float4* p, float4 v) {
    asm volatile("st.global.cs.v4.f32 [%0], {%1,%2,%3,%4};"
                 :: "l"(p), "f"(v.x), "f"(v.y), "f"(v.z), "f"(v.w) : "memory");
}

__device__ __forceinline__ float red16(float v) {
    v += __shfl_xor_sync(0xffffffffu, v, 8);
    v += __shfl_xor_sync(0xffffffffu, v, 4);
    v += __shfl_xor_sync(0xffffffffu, v, 2);
    v += __shfl_xor_sync(0xffffffffu, v, 1);
    return v;
}

__global__ __launch_bounds__(256, 6) void ntm_kernel(
    const float4* __restrict__ memory,
    const float4* __restrict__ prev_w4,
    const float4* __restrict__ k,
    const float*  __restrict__ beta,
    const float*  __restrict__ g,
    const float*  __restrict__ s,
    const float*  __restrict__ y,
    const float4* __restrict__ e4,
    const float4* __restrict__ a4,
    float*  __restrict__ out_read,
    float4* __restrict__ out_mem,
    float4* __restrict__ out_w4)
{
    __shared__ float4 tile[2048];          // 32 KB (updated in place, bulk-stored)
    __shared__ float4 rbuf4[128];          // 2 KB (warp-half-reduced partials)
    __shared__ float  logit[NN];
    __shared__ float  swf[NN];
    __shared__ unsigned long long mbar[NCHUNK];

    const int b  = blockIdx.x;
    const int t  = threadIdx.x;
    const int gg = t & 15;                 // quad-column owned
    const int j  = t >> 4;                 // rows n = 16*i + j
    const int lane = t & 31;
    const int wrp  = t >> 5;

    if (t < NCHUNK) mbar_init(su32(&mbar[t]), 1);
    __syncthreads();
    if (t < NCHUNK) {
        // each of 8 threads issues its own chunk: parallel DMA issuance
        const float4* src = memory + (size_t)b * 2048 + t * 256;
        unsigned m = su32(&mbar[t]);
        mbar_expect_tx(m, CHUNK_BYTES);
        bulk_ld_pol(su32(&tile[t * 256]), src, CHUNK_BYTES, m, mk_evict_first());
    }

    // prefetch small operands while the bulk copies are in flight
    pref_l2(&e4[b * 16 + gg]);
    pref_l2(&a4[b * 16 + gg]);
    const float4 kq = __ldg(&k[b * 16 + gg]);
    float betab = 0.f, gb = 0.f, yb = 0.f, s0 = 0.f, s1 = 0.f, s2 = 0.f;
    float4 pw = make_float4(0.f, 0.f, 0.f, 0.f);
    if (t < 32) {
        betab = __ldg(&beta[b]); gb = __ldg(&g[b]); yb = __ldg(&y[b]);
        s0 = __ldg(&s[0]); s1 = __ldg(&s[1]); s2 = __ldg(&s[2]);
        pw = __ldg(&prev_w4[b * 32 + t]);
    }

    // --- pass 1: per-row dot & |m|^2, chunk-interleaved waits (1 iter/chunk) ---
    {
        float ksq   = red16(kq.x*kq.x + kq.y*kq.y + kq.z*kq.z + kq.w*kq.w);
        float knorm = fmaxf(sqrtf(ksq), 1e-8f);
        #pragma unroll
        for (int i = 0; i < NCHUNK; i++) {
            mbar_wait0(su32(&mbar[i]));
            float4 vv = tile[i * 256 + t];
            float d  = vv.x*kq.x + vv.y*kq.y + vv.z*kq.z + vv.w*kq.w;
            float ms = vv.x*vv.x + vv.y*vv.y + vv.z*vv.z + vv.w*vv.w;
            d  = red16(d);
            ms = red16(ms);
            if (gg == 2 * i)
                logit[16 * i + j] = d / (knorm * fmaxf(sqrtf(ms), 1e-8f));
        }
    }
    __syncthreads();

    // --- mid-phase: warp 0 only, lane l owns rows 4l..4l+3 (MUFU fast-math) ---
    if (t < 32) {
        const float4 lg = ((const float4*)logit)[t];
        float l0 = betab * lg.x, l1 = betab * lg.y,
              l2 = betab * lg.z, l3 = betab * lg.w;

        float mx = fmaxf(fmaxf(l0, l1), fmaxf(l2, l3));
        #pragma unroll
        for (int o = 16; o; o >>= 1) mx = fmaxf(mx, __shfl_xor_sync(0xffffffffu, mx, o));

        float e0 = __expf(l0 - mx), e1 = __expf(l1 - mx),
              e2 = __expf(l2 - mx), e3 = __expf(l3 - mx);
        float sden = (e0 + e1) + (e2 + e3);
        #pragma unroll
        for (int o = 16; o; o >>= 1) sden += __shfl_xor_sync(0xffffffffu, sden, o);
        float inv = 1.f / sden;
        float og = 1.f - gb;

        float w0 = gb * e0 * inv + og * pw.x;
        float w1 = gb * e1 * inv + og * pw.y;
        float w2 = gb * e2 * inv + og * pw.z;
        float w3 = gb * e3 * inv + og * pw.w;

        float left  = __shfl_sync(0xffffffffu, w3, (t + 31) & 31);
        float right = __shfl_sync(0xffffffffu, w0, (t + 1) & 31);

        float wt0 = s0 * left + s1 * w0 + s2 * w1;
        float wt1 = s0 * w0   + s1 * w1 + s2 * w2;
        float wt2 = s0 * w1   + s1 * w2 + s2 * w3;
        float wt3 = s0 * w2   + s1 * w3 + s2 * right;

        float p0 = __powf(wt0, yb), p1 = __powf(wt1, yb),
              p2 = __powf(wt2, yb), p3 = __powf(wt3, yb);
        float psum = (p0 + p1) + (p2 + p3);
        #pragma unroll
        for (int o = 16; o; o >>= 1) psum += __shfl_xor_sync(0xffffffffu, psum, o);
        float ip = 1.f / psum;

        float4 wf = make_float4(p0 * ip, p1 * ip, p2 * ip, p3 * ip);
        ((float4*)swf)[t] = wf;
        st_cs_f4(&out_w4[b * 32 + t], wf);
    }
    __syncthreads();

    // --- erase/add in place (LDS.128 + STS.128) + read accumulation ---
    {
        const float4 eq = __ldg(&e4[b * 16 + gg]);
        const float4 aq = __ldg(&a4[b * 16 + gg]);
        float4 racc = make_float4(0.f, 0.f, 0.f, 0.f);
        #pragma unroll
        for (int i = 0; i < 8; i++) {
            float wn = swf[16 * i + j];
            float4 vv = tile[i * 256 + t], o;
            o.x = vv.x * (1.f - wn * eq.x) + wn * aq.x;
            o.y = vv.y * (1.f - wn * eq.y) + wn * aq.y;
            o.z = vv.z * (1.f - wn * eq.z) + wn * aq.z;
            o.w = vv.w * (1.f - wn * eq.w) + wn * aq.w;
            tile[i * 256 + t] = o;         // in-place: same word, no hazard
            racc.x += wn * vv.x; racc.y += wn * vv.y;
            racc.z += wn * vv.z; racc.w += wn * vv.w;
        }
        // merge the two j-phases within each warp (lanes l and l+16 share gg)
        racc.x += __shfl_xor_sync(0xffffffffu, racc.x, 16);
        racc.y += __shfl_xor_sync(0xffffffffu, racc.y, 16);
        racc.z += __shfl_xor_sync(0xffffffffu, racc.z, 16);
        racc.w += __shfl_xor_sync(0xffffffffu, racc.w, 16);
        if (lane < 16) rbuf4[wrp * 16 + lane] = racc;
    }
    __syncthreads();

    // final read reduction first (overlaps with TMA store issue below)
    float rfin = 0.f;
    if (t < MM) {
        const float* rb = (const float*)rbuf4;
        #pragma unroll
        for (int w = 0; w < 8; w++) rfin += rb[w * 64 + t];
    }

    // one bulk store drains the whole updated tile via the TMA engine
    if (t == 0) {
        bulk_st_pol(out_mem + (size_t)b * 2048, su32(tile), TILE_BYTES, mk_evict_first());
        bulk_st_commit();
    }

    if (t < MM) st_cs_f(&out_read[b * MM + t], rfin);

    // smem must stay live until TMA has read it
    if (t == 0) bulk_st_wait_read();
}

extern "C" void kernel_launch(void* const* d_in, const int* in_sizes, int n_in,
                              void* d_out, int out_size)
{
    const float4* memory = (const float4*)d_in[0];
    const float4* prev_w = (const float4*)d_in[1];
    const float4* k      = (const float4*)d_in[2];
    const float*  beta   = (const float*)d_in[3];
    const float*  g      = (const float*)d_in[4];
    const float*  s      = (const float*)d_in[5];
    const float*  y      = (const float*)d_in[6];
    const float4* e      = (const float4*)d_in[7];
    const float4* a      = (const float4*)d_in[8];

    float* out = (float*)d_out;
    float*  out_read = out;
    float4* out_mem  = (float4*)(out + (size_t)BB * MM);
    float4* out_w    = (float4*)(out + (size_t)BB * MM + (size_t)BB * NN * MM);

    ntm_kernel<<<BB, 256>>>(memory, prev_w, k, beta, g, s, y, e, a,
                            out_read, out_mem, out_w);
}